// round 15
// baseline (speedup 1.0000x reference)
#include <cuda_runtime.h>
#include <cuda_fp16.h>
#include <math.h>
#include <stdint.h>

// Problem dims (fixed)
#define NT 8192   // tokens
#define NH 1024   // hidden
#define NE 8      // experts
#define NI 1408   // intermediate

#define KC 64     // K halfs per pipeline stage
#define NSTAGE 3
#define PADH 72   // A smem row pitch (halfs); 144B -> ldmatrix banks conflict-free
#define GU_PADN 136  // gateup B row pitch (halfs); 272B % 128 = 16 -> conflict-free
#define DN_PADN 264  // down   B row pitch (halfs); 528B % 128 = 16 -> conflict-free

// gateup stage (halfs): A[128][72] + Bg[64 k][136 n] + Bu[64][136]
#define GU_BG_OFF (128 * PADH)                        // 9216
#define GU_BU_OFF (GU_BG_OFF + KC * GU_PADN)          // 17920
#define GU_STAGE  (GU_BU_OFF + KC * GU_PADN)          // 26624 halfs
#define GU_SMEM_BYTES (NSTAGE * GU_STAGE * 2)         // 159744

// down stage (halfs): A[128][72] + B[64 k][264 n]
#define DN_B_OFF  (128 * PADH)                        // 9216
#define DN_STAGE  (DN_B_OFF + KC * DN_PADN)           // 26112 halfs
#define DN_SMEM_BYTES (NSTAGE * DN_STAGE * 2)         // 156672

// ---------------- scratch (device globals) ----------------------------------
__device__ __half g_xh [(size_t)NT*NH];          // fp16 x (row-major, k-contig)
__device__ __half g_egh[(size_t)NE*NH*NI];       // fp16 weights, NATURAL layout [K][N]
__device__ __half g_euh[(size_t)NE*NH*NI];
__device__ __half g_edh[(size_t)NE*NI*NH];
__device__ __half g_sgh[(size_t)NH*NI];
__device__ __half g_suh[(size_t)NH*NI];
__device__ __half g_sdh[(size_t)NI*NH];
__device__ __half g_hbuf[(size_t)NE*NT*NI];
__device__ __half g_shh [(size_t)NT*NI];
__device__ float  g_down[(size_t)2*NT*NH];
__device__ int    g_rowlist[NE*NT];
__device__ int    g_pidlist[NE*NT];
__device__ int    g_cnt[NE];                     // zero at entry; re-zeroed at END
__device__ float  g_w[NT*2];

// ---------------- helpers ----------------------------------------------------
__device__ __forceinline__ uint32_t smem_u32(const void* p) {
    uint32_t a;
    asm("{ .reg .u64 t; cvta.to.shared.u64 t, %1; cvt.u32.u64 %0, t; }" : "=r"(a) : "l"(p));
    return a;
}
__device__ __forceinline__ void cpa16(uint32_t dst, const void* src) {
    asm volatile("cp.async.cg.shared.global [%0], [%1], 16;" :: "r"(dst), "l"(src) : "memory");
}
__device__ __forceinline__ void cp_commit() {
    asm volatile("cp.async.commit_group;" ::: "memory");
}
__device__ __forceinline__ void mma_f16(float* c, const uint32_t* a, const uint32_t* b) {
    asm volatile(
        "mma.sync.aligned.m16n8k16.row.col.f32.f16.f16.f32 "
        "{%0,%1,%2,%3}, {%4,%5,%6,%7}, {%8,%9}, {%0,%1,%2,%3};"
        : "+f"(c[0]), "+f"(c[1]), "+f"(c[2]), "+f"(c[3])
        : "r"(a[0]), "r"(a[1]), "r"(a[2]), "r"(a[3]), "r"(b[0]), "r"(b[1]));
}
__device__ __forceinline__ void ldsm4(uint32_t addr, uint32_t& r0, uint32_t& r1,
                                      uint32_t& r2, uint32_t& r3) {
    asm volatile("ldmatrix.sync.aligned.m8n8.x4.shared.b16 {%0,%1,%2,%3}, [%4];"
                 : "=r"(r0), "=r"(r1), "=r"(r2), "=r"(r3) : "r"(addr));
}
__device__ __forceinline__ void ldsm4t(uint32_t addr, uint32_t& r0, uint32_t& r1,
                                       uint32_t& r2, uint32_t& r3) {
    asm volatile("ldmatrix.sync.aligned.m8n8.x4.trans.shared.b16 {%0,%1,%2,%3}, [%4];"
                 : "=r"(r0), "=r"(r1), "=r"(r2), "=r"(r3) : "r"(addr));
}

// ---------------- small kernels ----------------------------------------------
__global__ void zero_cnt_kernel() {
    if (threadIdx.x < NE) g_cnt[threadIdx.x] = 0;
}

// elementwise f32 -> f16 over ALL tensors in one grid-stride pass (float4 units)
#define C_X   2097152u
#define C_EG  (C_X  + 2883584u)
#define C_EU  (C_EG + 2883584u)
#define C_ED  (C_EU + 2883584u)
#define C_SG  (C_ED + 360448u)
#define C_SU  (C_SG + 360448u)
#define C_SD  (C_SU + 360448u)
__global__ void cvt_all_kernel(const float* __restrict__ x,
                               const float* __restrict__ eg, const float* __restrict__ eu,
                               const float* __restrict__ ed, const float* __restrict__ sg,
                               const float* __restrict__ su, const float* __restrict__ sd) {
    for (uint32_t i = blockIdx.x * blockDim.x + threadIdx.x; i < C_SD;
         i += gridDim.x * blockDim.x) {
        const float* src; __half* dst; uint32_t li;
        if      (i < C_X)  { src = x;  dst = g_xh;  li = i; }
        else if (i < C_EG) { src = eg; dst = g_egh; li = i - C_X; }
        else if (i < C_EU) { src = eu; dst = g_euh; li = i - C_EG; }
        else if (i < C_ED) { src = ed; dst = g_edh; li = i - C_EU; }
        else if (i < C_SG) { src = sg; dst = g_sgh; li = i - C_ED; }
        else if (i < C_SU) { src = su; dst = g_suh; li = i - C_SG; }
        else               { src = sd; dst = g_sdh; li = i - C_SU; }
        float4 v = reinterpret_cast<const float4*>(src)[li];
        __half2 lo = __floats2half2_rn(v.x, v.y);
        __half2 hi = __floats2half2_rn(v.z, v.w);
        uint2 pk = make_uint2(*reinterpret_cast<uint32_t*>(&lo),
                              *reinterpret_cast<uint32_t*>(&hi));
        reinterpret_cast<uint2*>(dst)[li] = pk;
    }
}

// ---------------- router ------------------------------------------------------
__global__ void router_kernel(const float* __restrict__ x,
                              const float* __restrict__ gw) {
    int gtid = blockIdx.x * blockDim.x + threadIdx.x;
    int t    = gtid >> 5;
    int lane = gtid & 31;
    if (t >= NT) return;
    const float* xr = x + (size_t)t * NH;

    float acc[8] = {0.f,0.f,0.f,0.f,0.f,0.f,0.f,0.f};
    for (int h = lane; h < NH; h += 32) {
        float xv = __ldg(xr + h);
        const float4* g4 = reinterpret_cast<const float4*>(gw + (size_t)h * 8);
        float4 a = __ldg(g4 + 0);
        float4 b = __ldg(g4 + 1);
        acc[0] = fmaf(xv, a.x, acc[0]); acc[1] = fmaf(xv, a.y, acc[1]);
        acc[2] = fmaf(xv, a.z, acc[2]); acc[3] = fmaf(xv, a.w, acc[3]);
        acc[4] = fmaf(xv, b.x, acc[4]); acc[5] = fmaf(xv, b.y, acc[5]);
        acc[6] = fmaf(xv, b.z, acc[6]); acc[7] = fmaf(xv, b.w, acc[7]);
    }
    #pragma unroll
    for (int e = 0; e < 8; e++)
        #pragma unroll
        for (int off = 16; off > 0; off >>= 1)
            acc[e] += __shfl_xor_sync(0xffffffffu, acc[e], off);
    if (lane == 0) {
        float m = acc[0];
        #pragma unroll
        for (int e = 1; e < 8; e++) m = fmaxf(m, acc[e]);
        float p[8], s = 0.f;
        #pragma unroll
        for (int e = 0; e < 8; e++) { p[e] = expf(acc[e] - m); s += p[e]; }
        float inv = 1.f / s;
        #pragma unroll
        for (int e = 0; e < 8; e++) p[e] *= inv;
        int i0 = 0; float v0 = p[0];
        #pragma unroll
        for (int e = 1; e < 8; e++) if (p[e] > v0) { v0 = p[e]; i0 = e; }
        int i1 = -1; float v1 = -1.f;
        #pragma unroll
        for (int e = 0; e < 8; e++) if (e != i0 && p[e] > v1) { v1 = p[e]; i1 = e; }
        float denom = v0 + v1 + 1e-6f;
        g_w[2*t]   = v0 / denom;
        g_w[2*t+1] = v1 / denom;
        int r0 = atomicAdd(&g_cnt[i0], 1);
        g_rowlist[i0*NT + r0] = t; g_pidlist[i0*NT + r0] = 2*t;
        int r1 = atomicAdd(&g_cnt[i1], 1);
        g_rowlist[i1*NT + r1] = t; g_pidlist[i1*NT + r1] = 2*t + 1;
    }
}

// ---------------- gate+up SwiGLU GEMM (weights in natural [K][N], ldsm.trans) --
// grid (11, 64, 9): z<8 -> expert z, z==8 -> shared.
// Block 128(M) x 128(N per matrix). 8 warps, warp tile 64x32 per matrix.
__global__ __launch_bounds__(256, 1)
void gateup_all(const __half* __restrict__ egh, const __half* __restrict__ euh,
                const __half* __restrict__ sgh, const __half* __restrict__ suh) {
    extern __shared__ __align__(16) char dsm[];
    const int z = blockIdx.z;
    const bool shexp = (z == NE);
    const int e = shexp ? 0 : z;
    const int M = shexp ? NT : g_cnt[e];
    const int row0 = blockIdx.y * 128;
    if (row0 >= M) return;
    const int col0 = blockIdx.x * 128;

    const __half* wg = shexp ? sgh : egh + (size_t)e * NH * NI;   // [K=NH][N=NI]
    const __half* wu = shexp ? suh : euh + (size_t)e * NH * NI;
    __half* Hout = shexp ? g_shh : (g_hbuf + (size_t)e * NT * NI);

    const int tid = threadIdx.x, wid = tid >> 5, lane = tid & 31;
    const uint32_t sbase = smem_u32(dsm);

    // copy roles: A threads (tid<128): x row, 8x16B; B threads: one k-row, 16x16B
    const __half* s0;
    uint32_t d0;
    size_t bstep = 0;           // source advance per stage for B threads
    int nchunk;
    if (tid < 128) {
        int r = tid;
        int li = row0 + r; if (li >= M) li = M - 1;
        int gr = shexp ? li : g_rowlist[e*NT + li];
        s0 = g_xh + (size_t)gr * NH;       // advance handled via koff (k-contig)
        d0 = (uint32_t)r * PADH;
        nchunk = 8;
    } else if (tid < 192) {
        int u = tid - 128;                 // k-row u of Bg
        s0 = wg + (size_t)u * NI + col0;
        d0 = GU_BG_OFF + (uint32_t)u * GU_PADN;
        bstep = (size_t)KC * NI;
        nchunk = 16;
    } else {
        int u = tid - 192;
        s0 = wu + (size_t)u * NI + col0;
        d0 = GU_BU_OFF + (uint32_t)u * GU_PADN;
        bstep = (size_t)KC * NI;
        nchunk = 16;
    }
    const bool isA = (tid < 128);

    float accg[4][4][4], accu[4][4][4];
    #pragma unroll
    for (int i = 0; i < 4; i++)
        #pragma unroll
        for (int j = 0; j < 4; j++)
            #pragma unroll
            for (int q = 0; q < 4; q++) { accg[i][j][q] = 0.f; accu[i][j][q] = 0.f; }

    const int m0 = (wid & 1) * 64, n0 = (wid >> 1) * 32;
    const int tg = lane >> 2, ti = lane & 3;

    const int q8 = lane >> 3, l7 = lane & 7;
    // A: normal ldmatrix on [m][k] rows
    const uint32_t aoff  = (uint32_t)((m0 + (q8 & 1)*8 + l7) * PADH + (q8 >> 1)*8) * 2;
    // B: trans ldmatrix on [k][n] rows: lane -> k-row (q8&1)*8+l7, n-col n0+(q8>>1)*8
    const uint32_t bgoff = (uint32_t)(GU_BG_OFF + ((q8 & 1)*8 + l7) * GU_PADN + n0 + (q8 >> 1)*8) * 2;
    const uint32_t buoff = (uint32_t)(GU_BU_OFF + ((q8 & 1)*8 + l7) * GU_PADN + n0 + (q8 >> 1)*8) * 2;

    int koff = 0;
    #pragma unroll
    for (int s = 0; s < NSTAGE - 1; s++) {
        uint32_t base = sbase + (uint32_t)(s * GU_STAGE) * 2 + d0*2;
        if (isA) {
            #pragma unroll
            for (int c = 0; c < 8; c++) cpa16(base + c*16, s0 + koff + c*8);
        } else {
            #pragma unroll
            for (int c = 0; c < 16; c++) cpa16(base + c*16, s0 + c*8);
            s0 += bstep;
        }
        cp_commit();
        koff += KC;
    }

    uint32_t a[2][4][4], bg[2][4][2], bu[2][4][2];

    const int KST = NH / KC;   // 16
    for (int j = 0; j < KST; j++) {
        if (j < KST - 1) asm volatile("cp.async.wait_group 1;" ::: "memory");
        else             asm volatile("cp.async.wait_group 0;" ::: "memory");
        __syncthreads();
        const uint32_t stg = sbase + (uint32_t)((j % NSTAGE) * GU_STAGE) * 2;

        #pragma unroll
        for (int i = 0; i < 4; i++)
            ldsm4(stg + aoff + (uint32_t)(i*16*PADH)*2,
                  a[0][i][0], a[0][i][1], a[0][i][2], a[0][i][3]);
        #pragma unroll
        for (int jp = 0; jp < 2; jp++) {
            ldsm4t(stg + bgoff + (uint32_t)(jp*16)*2,
                   bg[0][2*jp][0], bg[0][2*jp][1], bg[0][2*jp+1][0], bg[0][2*jp+1][1]);
            ldsm4t(stg + buoff + (uint32_t)(jp*16)*2,
                   bu[0][2*jp][0], bu[0][2*jp][1], bu[0][2*jp+1][0], bu[0][2*jp+1][1]);
        }

        if (j + NSTAGE - 1 < KST) {
            int s = (j + NSTAGE - 1) % NSTAGE;
            uint32_t base = sbase + (uint32_t)(s * GU_STAGE) * 2 + d0*2;
            if (isA) {
                #pragma unroll
                for (int c = 0; c < 8; c++) cpa16(base + c*16, s0 + koff + c*8);
            } else {
                #pragma unroll
                for (int c = 0; c < 16; c++) cpa16(base + c*16, s0 + c*8);
                s0 += bstep;
            }
            cp_commit();
            koff += KC;
        }

        #pragma unroll
        for (int kk = 0; kk < 4; kk++) {
            const int cur = kk & 1, nxt = cur ^ 1;
            if (kk < 3) {
                const uint32_t kbA = (uint32_t)((kk+1) * 16) * 2;
                const uint32_t kbB = (uint32_t)((kk+1) * 16 * GU_PADN) * 2;
                #pragma unroll
                for (int i = 0; i < 4; i++)
                    ldsm4(stg + aoff + (uint32_t)(i*16*PADH)*2 + kbA,
                          a[nxt][i][0], a[nxt][i][1], a[nxt][i][2], a[nxt][i][3]);
                #pragma unroll
                for (int jp = 0; jp < 2; jp++) {
                    ldsm4t(stg + bgoff + (uint32_t)(jp*16)*2 + kbB,
                           bg[nxt][2*jp][0], bg[nxt][2*jp][1], bg[nxt][2*jp+1][0], bg[nxt][2*jp+1][1]);
                    ldsm4t(stg + buoff + (uint32_t)(jp*16)*2 + kbB,
                           bu[nxt][2*jp][0], bu[nxt][2*jp][1], bu[nxt][2*jp+1][0], bu[nxt][2*jp+1][1]);
                }
            }
            #pragma unroll
            for (int jn = 0; jn < 4; jn++)
                #pragma unroll
                for (int i = 0; i < 4; i++) {
                    mma_f16(accg[i][jn], a[cur][i], bg[cur][jn]);
                    mma_f16(accu[i][jn], a[cur][i], bu[cur][jn]);
                }
        }
    }

    // epilogue: silu(g)*u -> fp16
    #pragma unroll
    for (int i = 0; i < 4; i++) {
        #pragma unroll
        for (int half_ = 0; half_ < 2; half_++) {
            int r = m0 + i*16 + half_*8 + tg;
            int lrow = row0 + r;
            if (lrow < M) {
                __half* hrow = Hout + (size_t)lrow * NI + col0 + n0;
                #pragma unroll
                for (int jn = 0; jn < 4; jn++) {
                    float g0 = accg[i][jn][half_*2+0], g1 = accg[i][jn][half_*2+1];
                    float u0 = accu[i][jn][half_*2+0], u1 = accu[i][jn][half_*2+1];
                    float h0 = g0 / (1.f + expf(-g0)) * u0;
                    float h1 = g1 / (1.f + expf(-g1)) * u1;
                    __half2 hv = __floats2half2_rn(h0, h1);
                    *reinterpret_cast<__half2*>(hrow + jn*8 + 2*ti) = hv;
                }
            }
        }
    }
}

// ---------------- down GEMM (weights in natural [K][N], ldsm.trans) ------------
// grid (4, 64, 9): z<8 -> expert z (scatter), z==8 -> shared (direct).
// Block 128(M) x 256(N). 8 warps, warp tile 64x64.
__global__ __launch_bounds__(256, 1)
void down_all(const __half* __restrict__ edh, const __half* __restrict__ sdh,
              float* __restrict__ outp) {
    extern __shared__ __align__(16) char dsm[];
    const int z = blockIdx.z;
    const bool shexp = (z == NE);
    const int e = shexp ? 0 : z;
    const int M = shexp ? NT : g_cnt[e];
    const int row0 = blockIdx.y * 128;
    if (row0 >= M) return;
    const int col0 = blockIdx.x * 256;

    const __half* A  = shexp ? g_shh : (g_hbuf + (size_t)e * NT * NI);
    const __half* wd = shexp ? sdh : edh + (size_t)e * NI * NH;   // [K=NI][N=NH]

    const int tid = threadIdx.x, wid = tid >> 5, lane = tid & 31;
    const uint32_t sbase = smem_u32(dsm);

    const __half* s0;
    uint32_t d0;
    size_t bstep = 0;
    if (tid < 128) {
        int r = tid;
        int ar = row0 + r; if (ar >= M) ar = M - 1;
        s0 = A + (size_t)ar * NI;
        d0 = (uint32_t)r * PADH;
    } else {
        int u = tid - 128;                 // 128 threads: k-row u>>1, n-half u&1
        int kr = u >> 1, nh = u & 1;
        s0 = wd + (size_t)kr * NH + col0 + nh * 128;
        d0 = DN_B_OFF + (uint32_t)kr * DN_PADN + nh * 128;
        bstep = (size_t)KC * NH;
    }
    const bool isA = (tid < 128);

    float acc[4][8][4];
    #pragma unroll
    for (int i = 0; i < 4; i++)
        #pragma unroll
        for (int j = 0; j < 8; j++)
            #pragma unroll
            for (int q = 0; q < 4; q++) acc[i][j][q] = 0.f;

    const int m0 = (wid & 1) * 64, n0 = (wid >> 1) * 64;
    const int tg = lane >> 2, ti = lane & 3;

    const int q8 = lane >> 3, l7 = lane & 7;
    const uint32_t aoff = (uint32_t)((m0 + (q8 & 1)*8 + l7) * PADH + (q8 >> 1)*8) * 2;
    const uint32_t boff = (uint32_t)(DN_B_OFF + ((q8 & 1)*8 + l7) * DN_PADN + n0 + (q8 >> 1)*8) * 2;

    int koff = 0;
    #pragma unroll
    for (int s = 0; s < NSTAGE - 1; s++) {
        uint32_t base = sbase + (uint32_t)(s * DN_STAGE) * 2 + d0*2;
        if (isA) {
            #pragma unroll
            for (int c = 0; c < 8; c++) cpa16(base + c*16, s0 + koff + c*8);
        } else {
            #pragma unroll
            for (int c = 0; c < 16; c++) cpa16(base + c*16, s0 + c*8);
            s0 += bstep;
        }
        cp_commit();
        koff += KC;
    }

    uint32_t a[2][4][4], b[2][8][2];

    const int KST = NI / KC;   // 22
    for (int j = 0; j < KST; j++) {
        if (j < KST - 1) asm volatile("cp.async.wait_group 1;" ::: "memory");
        else             asm volatile("cp.async.wait_group 0;" ::: "memory");
        __syncthreads();
        const uint32_t stg = sbase + (uint32_t)((j % NSTAGE) * DN_STAGE) * 2;

        #pragma unroll
        for (int i = 0; i < 4; i++)
            ldsm4(stg + aoff + (uint32_t)(i*16*PADH)*2,
                  a[0][i][0], a[0][i][1], a[0][i][2], a[0][i][3]);
        #pragma unroll
        for (int jp = 0; jp < 4; jp++)
            ldsm4t(stg + boff + (uint32_t)(jp*16)*2,
                   b[0][2*jp][0], b[0][2*jp][1], b[0][2*jp+1][0], b[0][2*jp+1][1]);

        if (j + NSTAGE - 1 < KST) {
            int s = (j + NSTAGE - 1) % NSTAGE;
            uint32_t base = sbase + (uint32_t)(s * DN_STAGE) * 2 + d0*2;
            if (isA) {
                #pragma unroll
                for (int c = 0; c < 8; c++) cpa16(base + c*16, s0 + koff + c*8);
            } else {
                #pragma unroll
                for (int c = 0; c < 16; c++) cpa16(base + c*16, s0 + c*8);
                s0 += bstep;
            }
            cp_commit();
            koff += KC;
        }

        #pragma unroll
        for (int kk = 0; kk < 4; kk++) {
            const int cur = kk & 1, nxt = cur ^ 1;
            if (kk < 3) {
                const uint32_t kbA = (uint32_t)((kk+1) * 16) * 2;
                const uint32_t kbB = (uint32_t)((kk+1) * 16 * DN_PADN) * 2;
                #pragma unroll
                for (int i = 0; i < 4; i++)
                    ldsm4(stg + aoff + (uint32_t)(i*16*PADH)*2 + kbA,
                          a[nxt][i][0], a[nxt][i][1], a[nxt][i][2], a[nxt][i][3]);
                #pragma unroll
                for (int jp = 0; jp < 4; jp++)
                    ldsm4t(stg + boff + (uint32_t)(jp*16)*2 + kbB,
                           b[nxt][2*jp][0], b[nxt][2*jp][1], b[nxt][2*jp+1][0], b[nxt][2*jp+1][1]);
            }
            #pragma unroll
            for (int jn = 0; jn < 8; jn++)
                #pragma unroll
                for (int i = 0; i < 4; i++)
                    mma_f16(acc[i][jn], a[cur][i], b[cur][jn]);
        }
    }

    #pragma unroll
    for (int i = 0; i < 4; i++) {
        #pragma unroll
        for (int half_ = 0; half_ < 2; half_++) {
            int r = m0 + i*16 + half_*8 + tg;
            int lrow = row0 + r;
            if (lrow < M) {
                float* crow;
                if (!shexp) crow = g_down + (size_t)g_pidlist[e*NT + lrow] * NH;
                else        crow = outp   + (size_t)lrow * NH;
                crow += col0 + n0;
                #pragma unroll
                for (int jn = 0; jn < 8; jn++) {
                    float2 v;
                    v.x = acc[i][jn][half_*2+0];
                    v.y = acc[i][jn][half_*2+1];
                    *reinterpret_cast<float2*>(crow + jn*8 + 2*ti) = v;
                }
            }
        }
    }
}

// ---------------- combine -------------------------------------------------------
__global__ void combine_kernel(float* __restrict__ outp) {
    int t = blockIdx.x;
    int i = threadIdx.x;
    float w0 = g_w[2*t], w1 = g_w[2*t+1];
    float4*       o = reinterpret_cast<float4*>(outp + (size_t)t * NH);
    const float4* a = reinterpret_cast<const float4*>(g_down + (size_t)(2*t)   * NH);
    const float4* b = reinterpret_cast<const float4*>(g_down + (size_t)(2*t+1) * NH);
    float4 ov = o[i], av = a[i], bv = b[i];
    ov.x = fmaf(w1, bv.x, fmaf(w0, av.x, ov.x));
    ov.y = fmaf(w1, bv.y, fmaf(w0, av.y, ov.y));
    ov.z = fmaf(w1, bv.z, fmaf(w0, av.z, ov.z));
    ov.w = fmaf(w1, bv.w, fmaf(w0, av.w, ov.w));
    o[i] = ov;
}

// ---------------- launch ----------------------------------------------------------
extern "C" void kernel_launch(void* const* d_in, const int* in_sizes, int n_in,
                              void* d_out, int out_size) {
    const float* x  = (const float*)d_in[0];
    const float* gw = (const float*)d_in[1];
    const float* eg = (const float*)d_in[2];
    const float* eu = (const float*)d_in[3];
    const float* ed = (const float*)d_in[4];
    const float* sg = (const float*)d_in[5];
    const float* su = (const float*)d_in[6];
    const float* sd = (const float*)d_in[7];
    float* out = (float*)d_out;

    static bool attr_done = false;
    if (!attr_done) {
        cudaFuncSetAttribute(gateup_all, cudaFuncAttributeMaxDynamicSharedMemorySize, GU_SMEM_BYTES);
        cudaFuncSetAttribute(down_all,   cudaFuncAttributeMaxDynamicSharedMemorySize, DN_SMEM_BYTES);
        attr_done = true;
    }

    __half *p_egh, *p_euh, *p_edh, *p_sgh, *p_suh, *p_sdh;
    cudaGetSymbolAddress((void**)&p_egh, g_egh);
    cudaGetSymbolAddress((void**)&p_euh, g_euh);
    cudaGetSymbolAddress((void**)&p_edh, g_edh);
    cudaGetSymbolAddress((void**)&p_sgh, g_sgh);
    cudaGetSymbolAddress((void**)&p_suh, g_suh);
    cudaGetSymbolAddress((void**)&p_sdh, g_sdh);

    // g_cnt is zero on entry (static zero-init on first call; zero_cnt_kernel
    // at the END of each invocation re-arms graph replays).
    router_kernel<<<NT/4, 128>>>(x, gw);                                   // 1
    cvt_all_kernel<<<1184, 256>>>(x, eg, eu, ed, sg, su, sd);              // 2
    gateup_all<<<dim3(NI/128, NT/128, NE+1), 256, GU_SMEM_BYTES>>>(p_egh, p_euh, p_sgh, p_suh); // 3
    down_all  <<<dim3(NH/256, NT/128, NE+1), 256, DN_SMEM_BYTES>>>(p_edh, p_sdh, out);          // 4
    combine_kernel<<<NT, 256>>>(out);                                      // 5
    zero_cnt_kernel<<<1, 32>>>();                                          // 6 (re-arm)
}

// round 16
// speedup vs baseline: 1.0456x; 1.0456x over previous
#include <cuda_runtime.h>
#include <cuda_fp16.h>
#include <math.h>
#include <stdint.h>

// Problem dims (fixed)
#define NT 8192   // tokens
#define NH 1024   // hidden
#define NE 8      // experts
#define NI 1408   // intermediate

#define KC 128    // K halfs per pipeline stage
#define NSTAGE 2
#define PADH 136  // halfs per smem row (272B; 272%128=16 -> ldmatrix banks conflict-free)

// gateup stage (halfs): A[128][136] + Bg[128][136] + Bu[128][136]
#define GU_BG_OFF (128 * PADH)
#define GU_BU_OFF (256 * PADH)
#define GU_STAGE  (384 * PADH)
#define GU_SMEM_BYTES (NSTAGE * GU_STAGE * 2)        // 208896

// down stage (halfs): A[128][136] + B[256][136]
#define DN_B_OFF  (128 * PADH)
#define DN_STAGE  (384 * PADH)
#define DN_SMEM_BYTES (NSTAGE * DN_STAGE * 2)        // 208896

// ---------------- scratch (device globals) ----------------------------------
__device__ __half g_xh [(size_t)NT*NH];
__device__ __half g_egT[(size_t)NE*NI*NH];       // fp16 weights, [N][K]
__device__ __half g_euT[(size_t)NE*NI*NH];
__device__ __half g_edT[(size_t)NE*NH*NI];
__device__ __half g_sgT[(size_t)NI*NH];
__device__ __half g_suT[(size_t)NI*NH];
__device__ __half g_sdT[(size_t)NH*NI];
__device__ __half g_hbuf[(size_t)NE*NT*NI];
__device__ __half g_shh [(size_t)NT*NI];
__device__ float  g_down[(size_t)2*NT*NH];
__device__ int    g_rowlist[NE*NT];
__device__ int    g_pidlist[NE*NT];
__device__ int    g_cnt[NE];                     // zero at entry; re-zeroed at END
__device__ float  g_w[NT*2];

// ---------------- helpers ----------------------------------------------------
__device__ __forceinline__ uint32_t smem_u32(const void* p) {
    uint32_t a;
    asm("{ .reg .u64 t; cvta.to.shared.u64 t, %1; cvt.u32.u64 %0, t; }" : "=r"(a) : "l"(p));
    return a;
}
__device__ __forceinline__ void cpa16(uint32_t dst, const void* src) {
    asm volatile("cp.async.cg.shared.global [%0], [%1], 16;" :: "r"(dst), "l"(src) : "memory");
}
__device__ __forceinline__ void cp_commit() {
    asm volatile("cp.async.commit_group;" ::: "memory");
}
__device__ __forceinline__ void mma_f16(float* c, const uint32_t* a, const uint32_t* b) {
    asm volatile(
        "mma.sync.aligned.m16n8k16.row.col.f32.f16.f16.f32 "
        "{%0,%1,%2,%3}, {%4,%5,%6,%7}, {%8,%9}, {%0,%1,%2,%3};"
        : "+f"(c[0]), "+f"(c[1]), "+f"(c[2]), "+f"(c[3])
        : "r"(a[0]), "r"(a[1]), "r"(a[2]), "r"(a[3]), "r"(b[0]), "r"(b[1]));
}
__device__ __forceinline__ void ldsm4(uint32_t addr, uint32_t& r0, uint32_t& r1,
                                      uint32_t& r2, uint32_t& r3) {
    asm volatile("ldmatrix.sync.aligned.m8n8.x4.shared.b16 {%0,%1,%2,%3}, [%4];"
                 : "=r"(r0), "=r"(r1), "=r"(r2), "=r"(r3) : "r"(addr));
}

// ---------------- small kernels ----------------------------------------------
__global__ void zero_cnt_kernel() {
    if (threadIdx.x < NE) g_cnt[threadIdx.x] = 0;
}

// ---------------- merged prep: cvt(x) + 6 transpose-converts in ONE grid ------
#define PREP_BLOCKS 19520
__global__ void prep_kernel(const float* __restrict__ x,
                            const float* __restrict__ eg, const float* __restrict__ eu,
                            const float* __restrict__ ed, const float* __restrict__ sg,
                            const float* __restrict__ su, const float* __restrict__ sd) {
    __shared__ float tile[32][65];
    int b = blockIdx.x;
    int tx = threadIdx.x, ty = threadIdx.y;

    if (b < 512) {           // cvt x
        int tid = ty * 32 + tx;
        int n4 = NT * NH / 4;
        for (int i = b * 256 + tid; i < n4; i += 512 * 256) {
            float4 v = reinterpret_cast<const float4*>(x)[i];
            __half2 lo = __floats2half2_rn(v.x, v.y);
            __half2 hi = __floats2half2_rn(v.z, v.w);
            uint2 pk = make_uint2(*reinterpret_cast<uint32_t*>(&lo),
                                  *reinterpret_cast<uint32_t*>(&hi));
            reinterpret_cast<uint2*>(g_xh)[i] = pk;
        }
        return;
    }
    b -= 512;

    const float* in; __half* outp; int R, C, bx, by, bz;
    if (b < 5632) {
        in = eg; outp = g_egT; R = NH; C = NI;
        bz = b / 704; int r = b % 704; bx = r % 44; by = r / 44;
    } else if (b < 11264) {
        b -= 5632; in = eu; outp = g_euT; R = NH; C = NI;
        bz = b / 704; int r = b % 704; bx = r % 44; by = r / 44;
    } else if (b < 16896) {
        b -= 11264; in = ed; outp = g_edT; R = NI; C = NH;
        bz = b / 704; int r = b % 704; bx = r % 32; by = r / 32;
    } else if (b < 17600) {
        b -= 16896; in = sg; outp = g_sgT; R = NH; C = NI;
        bz = 0; bx = b % 44; by = b / 44;
    } else if (b < 18304) {
        b -= 17600; in = su; outp = g_suT; R = NH; C = NI;
        bz = 0; bx = b % 44; by = b / 44;
    } else {
        b -= 18304; in = sd; outp = g_sdT; R = NI; C = NH;
        bz = 0; bx = b % 32; by = b / 32;
    }

    size_t boff = (size_t)bz * R * C;
    const float* ib = in + boff;
    __half* ob = outp + boff;
    int c0 = bx * 32, r0 = by * 64;
    #pragma unroll
    for (int i = 0; i < 8; i++) {
        int r = ty + 8*i;
        tile[tx][r] = ib[(size_t)(r0 + r) * C + c0 + tx];
    }
    __syncthreads();
    #pragma unroll
    for (int ic = 0; ic < 4; ic++) {
        int c = ty + 8*ic;
        __half2 v = __floats2half2_rn(tile[c][2*tx], tile[c][2*tx+1]);
        *reinterpret_cast<__half2*>(ob + (size_t)(c0 + c) * R + r0 + 2*tx) = v;
    }
}

// ---------------- router ------------------------------------------------------
__global__ void router_kernel(const float* __restrict__ x,
                              const float* __restrict__ gw) {
    int gtid = blockIdx.x * blockDim.x + threadIdx.x;
    int t    = gtid >> 5;
    int lane = gtid & 31;
    if (t >= NT) return;
    const float* xr = x + (size_t)t * NH;

    float acc[8] = {0.f,0.f,0.f,0.f,0.f,0.f,0.f,0.f};
    for (int h = lane; h < NH; h += 32) {
        float xv = __ldg(xr + h);
        const float4* g4 = reinterpret_cast<const float4*>(gw + (size_t)h * 8);
        float4 a = __ldg(g4 + 0);
        float4 b = __ldg(g4 + 1);
        acc[0] = fmaf(xv, a.x, acc[0]); acc[1] = fmaf(xv, a.y, acc[1]);
        acc[2] = fmaf(xv, a.z, acc[2]); acc[3] = fmaf(xv, a.w, acc[3]);
        acc[4] = fmaf(xv, b.x, acc[4]); acc[5] = fmaf(xv, b.y, acc[5]);
        acc[6] = fmaf(xv, b.z, acc[6]); acc[7] = fmaf(xv, b.w, acc[7]);
    }
    #pragma unroll
    for (int e = 0; e < 8; e++)
        #pragma unroll
        for (int off = 16; off > 0; off >>= 1)
            acc[e] += __shfl_xor_sync(0xffffffffu, acc[e], off);
    if (lane == 0) {
        float m = acc[0];
        #pragma unroll
        for (int e = 1; e < 8; e++) m = fmaxf(m, acc[e]);
        float p[8], s = 0.f;
        #pragma unroll
        for (int e = 0; e < 8; e++) { p[e] = expf(acc[e] - m); s += p[e]; }
        float inv = 1.f / s;
        #pragma unroll
        for (int e = 0; e < 8; e++) p[e] *= inv;
        int i0 = 0; float v0 = p[0];
        #pragma unroll
        for (int e = 1; e < 8; e++) if (p[e] > v0) { v0 = p[e]; i0 = e; }
        int i1 = -1; float v1 = -1.f;
        #pragma unroll
        for (int e = 0; e < 8; e++) if (e != i0 && p[e] > v1) { v1 = p[e]; i1 = e; }
        float denom = v0 + v1 + 1e-6f;
        g_w[2*t]   = v0 / denom;
        g_w[2*t+1] = v1 / denom;
        int r0 = atomicAdd(&g_cnt[i0], 1);
        g_rowlist[i0*NT + r0] = t; g_pidlist[i0*NT + r0] = 2*t;
        int r1 = atomicAdd(&g_cnt[i1], 1);
        g_rowlist[i1*NT + r1] = t; g_pidlist[i1*NT + r1] = 2*t + 1;
    }
}

// ---------------- gate+up SwiGLU GEMM: KC=128, 2-stage -------------------------
// grid (11, 64, 9): z<8 -> expert z, z==8 -> shared.
// Block 128(M) x 128(N per matrix). 8 warps, warp tile 64x32 per matrix.
__global__ __launch_bounds__(256, 1)
void gateup_all(const __half* __restrict__ egT, const __half* __restrict__ euT,
                const __half* __restrict__ sgT, const __half* __restrict__ suT) {
    extern __shared__ __align__(16) char dsm[];
    const int z = blockIdx.z;
    const bool shexp = (z == NE);
    const int e = shexp ? 0 : z;
    const int M = shexp ? NT : g_cnt[e];
    const int row0 = blockIdx.y * 128;
    if (row0 >= M) return;
    const int col0 = blockIdx.x * 128;

    const __half* wg = shexp ? sgT : egT + (size_t)e * NI * NH;
    const __half* wu = shexp ? suT : euT + (size_t)e * NI * NH;
    __half* Hout = shexp ? g_shh : (g_hbuf + (size_t)e * NT * NI);

    const int tid = threadIdx.x, wid = tid >> 5, lane = tid & 31;
    const uint32_t sbase = smem_u32(dsm);

    // copy roles: A threads one row (16 chunks); B threads two rows (16 each)
    const __half* s0; const __half* s1;
    uint32_t d0, d1;
    if (tid < 128) {
        int r = tid;
        int li = row0 + r; if (li >= M) li = M - 1;
        int gr = shexp ? li : g_rowlist[e*NT + li];
        s0 = s1 = g_xh + (size_t)gr * NH;
        d0 = d1 = (uint32_t)r * PADH;
    } else if (tid < 192) {
        int u = tid - 128;
        s0 = wg + (size_t)(col0 + u)      * NH;
        s1 = wg + (size_t)(col0 + u + 64) * NH;
        d0 = GU_BG_OFF + (uint32_t)u * PADH;
        d1 = GU_BG_OFF + (uint32_t)(u + 64) * PADH;
    } else {
        int u = tid - 192;
        s0 = wu + (size_t)(col0 + u)      * NH;
        s1 = wu + (size_t)(col0 + u + 64) * NH;
        d0 = GU_BU_OFF + (uint32_t)u * PADH;
        d1 = GU_BU_OFF + (uint32_t)(u + 64) * PADH;
    }
    const bool tworow = (tid >= 128);

    float accg[4][4][4], accu[4][4][4];
    #pragma unroll
    for (int i = 0; i < 4; i++)
        #pragma unroll
        for (int j = 0; j < 4; j++)
            #pragma unroll
            for (int q = 0; q < 4; q++) { accg[i][j][q] = 0.f; accu[i][j][q] = 0.f; }

    const int m0 = (wid & 1) * 64, n0 = (wid >> 1) * 32;
    const int tg = lane >> 2, ti = lane & 3;

    const int q8 = lane >> 3, l7 = lane & 7;
    const uint32_t aoff  = (uint32_t)((m0 + (q8 & 1)*8 + l7) * PADH + (q8 >> 1)*8) * 2;
    const uint32_t bgoff = (uint32_t)(GU_BG_OFF + (n0 + (q8 >> 1)*8 + l7) * PADH + (q8 & 1)*8) * 2;
    const uint32_t buoff = (uint32_t)(GU_BU_OFF + (n0 + (q8 >> 1)*8 + l7) * PADH + (q8 & 1)*8) * 2;

    // prologue: stage 0
    {
        uint32_t base = sbase;
        #pragma unroll
        for (int c = 0; c < 16; c++) cpa16(base + d0*2 + c*16, s0 + c*8);
        if (tworow) {
            #pragma unroll
            for (int c = 0; c < 16; c++) cpa16(base + d1*2 + c*16, s1 + c*8);
        }
        cp_commit();
    }

    uint32_t a[2][4][4], bg[2][4][2], bu[2][4][2];

    const int KST = NH / KC;   // 8
    for (int j = 0; j < KST; j++) {
        asm volatile("cp.async.wait_group 0;" ::: "memory");
        __syncthreads();
        const uint32_t stg = sbase + (uint32_t)((j & 1) * GU_STAGE) * 2;

        // prefetch kk=0 fragments (latency hides under next-stage cp.async burst)
        #pragma unroll
        for (int i = 0; i < 4; i++)
            ldsm4(stg + aoff + (uint32_t)(i*16*PADH)*2,
                  a[0][i][0], a[0][i][1], a[0][i][2], a[0][i][3]);
        #pragma unroll
        for (int jp = 0; jp < 2; jp++) {
            ldsm4(stg + bgoff + (uint32_t)(jp*16*PADH)*2,
                  bg[0][2*jp][0], bg[0][2*jp][1], bg[0][2*jp+1][0], bg[0][2*jp+1][1]);
            ldsm4(stg + buoff + (uint32_t)(jp*16*PADH)*2,
                  bu[0][2*jp][0], bu[0][2*jp][1], bu[0][2*jp+1][0], bu[0][2*jp+1][1]);
        }

        if (j + 1 < KST) {
            int koff = (j + 1) * KC;
            uint32_t base = sbase + (uint32_t)(((j + 1) & 1) * GU_STAGE) * 2;
            #pragma unroll
            for (int c = 0; c < 16; c++) cpa16(base + d0*2 + c*16, s0 + koff + c*8);
            if (tworow) {
                #pragma unroll
                for (int c = 0; c < 16; c++) cpa16(base + d1*2 + c*16, s1 + koff + c*8);
            }
            cp_commit();
        }

        #pragma unroll
        for (int kk = 0; kk < 8; kk++) {
            const int cur = kk & 1, nxt = cur ^ 1;
            if (kk < 7) {
                const uint32_t kb = (uint32_t)((kk+1) * 16) * 2;
                #pragma unroll
                for (int i = 0; i < 4; i++)
                    ldsm4(stg + aoff + (uint32_t)(i*16*PADH)*2 + kb,
                          a[nxt][i][0], a[nxt][i][1], a[nxt][i][2], a[nxt][i][3]);
                #pragma unroll
                for (int jp = 0; jp < 2; jp++) {
                    ldsm4(stg + bgoff + (uint32_t)(jp*16*PADH)*2 + kb,
                          bg[nxt][2*jp][0], bg[nxt][2*jp][1], bg[nxt][2*jp+1][0], bg[nxt][2*jp+1][1]);
                    ldsm4(stg + buoff + (uint32_t)(jp*16*PADH)*2 + kb,
                          bu[nxt][2*jp][0], bu[nxt][2*jp][1], bu[nxt][2*jp+1][0], bu[nxt][2*jp+1][1]);
                }
            }
            #pragma unroll
            for (int jn = 0; jn < 4; jn++)
                #pragma unroll
                for (int i = 0; i < 4; i++) {
                    mma_f16(accg[i][jn], a[cur][i], bg[cur][jn]);
                    mma_f16(accu[i][jn], a[cur][i], bu[cur][jn]);
                }
        }
    }

    // epilogue: silu(g)*u -> fp16
    #pragma unroll
    for (int i = 0; i < 4; i++) {
        #pragma unroll
        for (int half_ = 0; half_ < 2; half_++) {
            int r = m0 + i*16 + half_*8 + tg;
            int lrow = row0 + r;
            if (lrow < M) {
                __half* hrow = Hout + (size_t)lrow * NI + col0 + n0;
                #pragma unroll
                for (int jn = 0; jn < 4; jn++) {
                    float g0 = accg[i][jn][half_*2+0], g1 = accg[i][jn][half_*2+1];
                    float u0 = accu[i][jn][half_*2+0], u1 = accu[i][jn][half_*2+1];
                    float h0 = g0 / (1.f + expf(-g0)) * u0;
                    float h1 = g1 / (1.f + expf(-g1)) * u1;
                    __half2 hv = __floats2half2_rn(h0, h1);
                    *reinterpret_cast<__half2*>(hrow + jn*8 + 2*ti) = hv;
                }
            }
        }
    }
}

// ---------------- down GEMM: KC=128, 2-stage -----------------------------------
// grid (4, 64, 9): z<8 -> expert z (scatter), z==8 -> shared (direct).
// Block 128(M) x 256(N). 8 warps, warp tile 64x64.
__global__ __launch_bounds__(256, 1)
void down_all(const __half* __restrict__ edT, const __half* __restrict__ sdT,
              float* __restrict__ outp) {
    extern __shared__ __align__(16) char dsm[];
    const int z = blockIdx.z;
    const bool shexp = (z == NE);
    const int e = shexp ? 0 : z;
    const int M = shexp ? NT : g_cnt[e];
    const int row0 = blockIdx.y * 128;
    if (row0 >= M) return;
    const int col0 = blockIdx.x * 256;

    const __half* A  = shexp ? g_shh : (g_hbuf + (size_t)e * NT * NI);
    const __half* wd = shexp ? sdT : edT + (size_t)e * NH * NI;

    const int tid = threadIdx.x, wid = tid >> 5, lane = tid & 31;
    const uint32_t sbase = smem_u32(dsm);

    const __half* s0; const __half* s1;
    uint32_t d0, d1;
    if (tid < 128) {
        int r = tid;
        int ar = row0 + r; if (ar >= M) ar = M - 1;
        s0 = s1 = A + (size_t)ar * NI;
        d0 = d1 = (uint32_t)r * PADH;
    } else {
        int u = tid - 128;
        s0 = wd + (size_t)(col0 + u)       * NI;
        s1 = wd + (size_t)(col0 + u + 128) * NI;
        d0 = DN_B_OFF + (uint32_t)u * PADH;
        d1 = DN_B_OFF + (uint32_t)(u + 128) * PADH;
    }
    const bool tworow = (tid >= 128);

    float acc[4][8][4];
    #pragma unroll
    for (int i = 0; i < 4; i++)
        #pragma unroll
        for (int j = 0; j < 8; j++)
            #pragma unroll
            for (int q = 0; q < 4; q++) acc[i][j][q] = 0.f;

    const int m0 = (wid & 1) * 64, n0 = (wid >> 1) * 64;
    const int tg = lane >> 2, ti = lane & 3;

    const int q8 = lane >> 3, l7 = lane & 7;
    const uint32_t aoff = (uint32_t)((m0 + (q8 & 1)*8 + l7) * PADH + (q8 >> 1)*8) * 2;
    const uint32_t boff = (uint32_t)(DN_B_OFF + (n0 + (q8 >> 1)*8 + l7) * PADH + (q8 & 1)*8) * 2;

    // prologue: stage 0 (guard K tail: NI/KC = 11 exact)
    {
        uint32_t base = sbase;
        #pragma unroll
        for (int c = 0; c < 16; c++) cpa16(base + d0*2 + c*16, s0 + c*8);
        if (tworow) {
            #pragma unroll
            for (int c = 0; c < 16; c++) cpa16(base + d1*2 + c*16, s1 + c*8);
        }
        cp_commit();
    }

    uint32_t a[2][4][4], b[2][8][2];

    const int KST = NI / KC;   // 11
    for (int j = 0; j < KST; j++) {
        asm volatile("cp.async.wait_group 0;" ::: "memory");
        __syncthreads();
        const uint32_t stg = sbase + (uint32_t)((j & 1) * DN_STAGE) * 2;

        #pragma unroll
        for (int i = 0; i < 4; i++)
            ldsm4(stg + aoff + (uint32_t)(i*16*PADH)*2,
                  a[0][i][0], a[0][i][1], a[0][i][2], a[0][i][3]);
        #pragma unroll
        for (int jp = 0; jp < 4; jp++)
            ldsm4(stg + boff + (uint32_t)(jp*16*PADH)*2,
                  b[0][2*jp][0], b[0][2*jp][1], b[0][2*jp+1][0], b[0][2*jp+1][1]);

        if (j + 1 < KST) {
            int koff = (j + 1) * KC;
            uint32_t base = sbase + (uint32_t)(((j + 1) & 1) * DN_STAGE) * 2;
            #pragma unroll
            for (int c = 0; c < 16; c++) cpa16(base + d0*2 + c*16, s0 + koff + c*8);
            if (tworow) {
                #pragma unroll
                for (int c = 0; c < 16; c++) cpa16(base + d1*2 + c*16, s1 + koff + c*8);
            }
            cp_commit();
        }

        #pragma unroll
        for (int kk = 0; kk < 8; kk++) {
            const int cur = kk & 1, nxt = cur ^ 1;
            if (kk < 7) {
                const uint32_t kb = (uint32_t)((kk+1) * 16) * 2;
                #pragma unroll
                for (int i = 0; i < 4; i++)
                    ldsm4(stg + aoff + (uint32_t)(i*16*PADH)*2 + kb,
                          a[nxt][i][0], a[nxt][i][1], a[nxt][i][2], a[nxt][i][3]);
                #pragma unroll
                for (int jp = 0; jp < 4; jp++)
                    ldsm4(stg + boff + (uint32_t)(jp*16*PADH)*2 + kb,
                          b[nxt][2*jp][0], b[nxt][2*jp][1], b[nxt][2*jp+1][0], b[nxt][2*jp+1][1]);
            }
            #pragma unroll
            for (int jn = 0; jn < 8; jn++)
                #pragma unroll
                for (int i = 0; i < 4; i++)
                    mma_f16(acc[i][jn], a[cur][i], b[cur][jn]);
        }
    }

    #pragma unroll
    for (int i = 0; i < 4; i++) {
        #pragma unroll
        for (int half_ = 0; half_ < 2; half_++) {
            int r = m0 + i*16 + half_*8 + tg;
            int lrow = row0 + r;
            if (lrow < M) {
                float* crow;
                if (!shexp) crow = g_down + (size_t)g_pidlist[e*NT + lrow] * NH;
                else        crow = outp   + (size_t)lrow * NH;
                crow += col0 + n0;
                #pragma unroll
                for (int jn = 0; jn < 8; jn++) {
                    float2 v;
                    v.x = acc[i][jn][half_*2+0];
                    v.y = acc[i][jn][half_*2+1];
                    *reinterpret_cast<float2*>(crow + jn*8 + 2*ti) = v;
                }
            }
        }
    }
}

// ---------------- combine -------------------------------------------------------
__global__ void combine_kernel(float* __restrict__ outp) {
    int t = blockIdx.x;
    int i = threadIdx.x;
    float w0 = g_w[2*t], w1 = g_w[2*t+1];
    float4*       o = reinterpret_cast<float4*>(outp + (size_t)t * NH);
    const float4* a = reinterpret_cast<const float4*>(g_down + (size_t)(2*t)   * NH);
    const float4* b = reinterpret_cast<const float4*>(g_down + (size_t)(2*t+1) * NH);
    float4 ov = o[i], av = a[i], bv = b[i];
    ov.x = fmaf(w1, bv.x, fmaf(w0, av.x, ov.x));
    ov.y = fmaf(w1, bv.y, fmaf(w0, av.y, ov.y));
    ov.z = fmaf(w1, bv.z, fmaf(w0, av.z, ov.z));
    ov.w = fmaf(w1, bv.w, fmaf(w0, av.w, ov.w));
    o[i] = ov;
}

// ---------------- launch ----------------------------------------------------------
extern "C" void kernel_launch(void* const* d_in, const int* in_sizes, int n_in,
                              void* d_out, int out_size) {
    const float* x  = (const float*)d_in[0];
    const float* gw = (const float*)d_in[1];
    const float* eg = (const float*)d_in[2];
    const float* eu = (const float*)d_in[3];
    const float* ed = (const float*)d_in[4];
    const float* sg = (const float*)d_in[5];
    const float* su = (const float*)d_in[6];
    const float* sd = (const float*)d_in[7];
    float* out = (float*)d_out;

    static bool attr_done = false;
    if (!attr_done) {
        cudaFuncSetAttribute(gateup_all, cudaFuncAttributeMaxDynamicSharedMemorySize, GU_SMEM_BYTES);
        cudaFuncSetAttribute(down_all,   cudaFuncAttributeMaxDynamicSharedMemorySize, DN_SMEM_BYTES);
        attr_done = true;
    }

    __half *p_egT, *p_euT, *p_edT, *p_sgT, *p_suT, *p_sdT;
    cudaGetSymbolAddress((void**)&p_egT, g_egT);
    cudaGetSymbolAddress((void**)&p_euT, g_euT);
    cudaGetSymbolAddress((void**)&p_edT, g_edT);
    cudaGetSymbolAddress((void**)&p_sgT, g_sgT);
    cudaGetSymbolAddress((void**)&p_suT, g_suT);
    cudaGetSymbolAddress((void**)&p_sdT, g_sdT);

    // g_cnt is zero on entry (static zero-init on first call; zero_cnt_kernel
    // at the END of each invocation re-arms graph replays).
    router_kernel<<<NT/4, 128>>>(x, gw);                                   // 1
    prep_kernel<<<PREP_BLOCKS, dim3(32, 8)>>>(x, eg, eu, ed, sg, su, sd);  // 2
    gateup_all<<<dim3(NI/128, NT/128, NE+1), 256, GU_SMEM_BYTES>>>(p_egT, p_euT, p_sgT, p_suT); // 3
    down_all  <<<dim3(NH/256, NT/128, NE+1), 256, DN_SMEM_BYTES>>>(p_edT, p_sdT, out);          // 4
    combine_kernel<<<NT, 256>>>(out);                                      // 5
    zero_cnt_kernel<<<1, 32>>>();                                          // 6 (re-arm)
}